// round 8
// baseline (speedup 1.0000x reference)
#include <cuda_runtime.h>

// VecInt: scaling-and-squaring integration of a stationary velocity field.
// vec (1,3,160,192,160) fp32, nsteps=7.
//
// Round 8: quad-lane gather on a y-interleaved AoS layout.
// Layout: float4 voxel at ((z*96 + y/2)*W + x)*2 + (y&1)  — footprint
// unchanged. For even y0, the 4 (x,y) corners of a z-slice are 64 contiguous
// 32B-aligned bytes; with 4 lanes per voxel (dy=sub&1, dx=sub>>1) each
// z-slice is ONE gather instruction. Gather instrs 4->2 per voxel, scattered
// L1 wavefronts ~4.5 -> ~3.65 per voxel. Reduction via 2-level shfl.
// iter1 fused with SoA ingest (R7), last iter fused with SoA egress.

constexpr int D = 160;
constexpr int H = 192;
constexpr int W = 160;
constexpr int HP = H / 2;                // 96 y-pairs
constexpr int NVOX = D * H * W;          // 4,915,200
constexpr int NSTEPS = 7;

__device__ __align__(128) float4 g_bufA[NVOX];
__device__ __align__(128) float4 g_bufB[NVOX];

// interleaved-y address of voxel (x,y,z)
__device__ __forceinline__ int vaddr(int x, int y, int z) {
    return ((z * HP + (y >> 1)) * W + x) * 2 + (y & 1);
}

// ---------------------------------------------------------------------------
// Iteration 1, fused with SoA ingest + per-channel voxel-unit scaling.
// Block = one y-pair row: blockIdx.x = y-pair, blockIdx.y = z; 320 threads,
// t = x*2 + dy  (dy innermost so output stores are fully coalesced).
// ---------------------------------------------------------------------------
__global__ void __launch_bounds__(320)
iter1_kernel(const float* __restrict__ in, float4* __restrict__ out)
{
    int dy = threadIdx.x & 1;
    int x  = threadIdx.x >> 1;
    int y  = blockIdx.x * 2 + dy;
    int z  = blockIdx.y;
    int idx = (z * H + y) * W + x;       // linear (SoA source) index

    const float s  = 1.0f / 128.0f;          // 1/2^7
    const float sD = s * 0.5f * (D - 1);
    const float sH = s * 0.5f * (H - 1);
    const float sW = s * 0.5f * (W - 1);

    const float* p0 = in;
    const float* p1 = in + NVOX;
    const float* p2 = in + 2 * NVOX;

    float vx = p0[idx] * sD;
    float vy = p1[idx] * sH;
    float vz = p2[idx] * sW;

    float zf = (float)z + vx;
    float yf = (float)y + vy;
    float xf = (float)x + vz;

    int z0 = __float2int_rd(zf);
    int y0 = __float2int_rd(yf);
    int x0 = __float2int_rd(xf);
    float fz = zf - (float)z0;
    float fy = yf - (float)y0;
    float fx = xf - (float)x0;
    int z1 = z0 + 1, y1 = y0 + 1;

    float Wz0 = ((unsigned)z0 < (unsigned)D) ? (1.0f - fz) : 0.0f;
    float Wz1 = ((unsigned)z1 < (unsigned)D) ? fz          : 0.0f;
    float Wy0 = ((unsigned)y0 < (unsigned)H) ? (1.0f - fy) : 0.0f;
    float Wy1 = ((unsigned)y1 < (unsigned)H) ? fy          : 0.0f;
    float Wx0 = ((unsigned)x0 < (unsigned)W) ? (1.0f - fx) : 0.0f;
    float Wx1 = ((unsigned)(x0 + 1) < (unsigned)W) ? fx    : 0.0f;

    int zc0 = min(max(z0, 0), D - 1), zc1 = min(max(z1, 0), D - 1);
    int yc0 = min(max(y0, 0), H - 1), yc1 = min(max(y1, 0), H - 1);
    int xc0 = min(max(x0, 0), W - 1), xc1 = min(max(x0 + 1, 0), W - 1);

    int r00 = (zc0 * H + yc0) * W;
    int r01 = (zc0 * H + yc1) * W;
    int r10 = (zc1 * H + yc0) * W;
    int r11 = (zc1 * H + yc1) * W;

    float px, py, pz;
    {
        const float* p = p0; const float sc = sD;
        float c00a = p[r00 + xc0] * sc, c00b = p[r00 + xc1] * sc;
        float c01a = p[r01 + xc0] * sc, c01b = p[r01 + xc1] * sc;
        float c10a = p[r10 + xc0] * sc, c10b = p[r10 + xc1] * sc;
        float c11a = p[r11 + xc0] * sc, c11b = p[r11 + xc1] * sc;
        float a0A = fmaf(c01a, Wy1, c00a * Wy0);
        float a1A = fmaf(c11a, Wy1, c10a * Wy0);
        float a0B = fmaf(c01b, Wy1, c00b * Wy0);
        float a1B = fmaf(c11b, Wy1, c10b * Wy0);
        px = Wx0 * fmaf(a1A, Wz1, a0A * Wz0)
           + Wx1 * fmaf(a1B, Wz1, a0B * Wz0);
    }
    {
        const float* p = p1; const float sc = sH;
        float c00a = p[r00 + xc0] * sc, c00b = p[r00 + xc1] * sc;
        float c01a = p[r01 + xc0] * sc, c01b = p[r01 + xc1] * sc;
        float c10a = p[r10 + xc0] * sc, c10b = p[r10 + xc1] * sc;
        float c11a = p[r11 + xc0] * sc, c11b = p[r11 + xc1] * sc;
        float a0A = fmaf(c01a, Wy1, c00a * Wy0);
        float a1A = fmaf(c11a, Wy1, c10a * Wy0);
        float a0B = fmaf(c01b, Wy1, c00b * Wy0);
        float a1B = fmaf(c11b, Wy1, c10b * Wy0);
        py = Wx0 * fmaf(a1A, Wz1, a0A * Wz0)
           + Wx1 * fmaf(a1B, Wz1, a0B * Wz0);
    }
    {
        const float* p = p2; const float sc = sW;
        float c00a = p[r00 + xc0] * sc, c00b = p[r00 + xc1] * sc;
        float c01a = p[r01 + xc0] * sc, c01b = p[r01 + xc1] * sc;
        float c10a = p[r10 + xc0] * sc, c10b = p[r10 + xc1] * sc;
        float c11a = p[r11 + xc0] * sc, c11b = p[r11 + xc1] * sc;
        float a0A = fmaf(c01a, Wy1, c00a * Wy0);
        float a1A = fmaf(c11a, Wy1, c10a * Wy0);
        float a0B = fmaf(c01b, Wy1, c00b * Wy0);
        float a1B = fmaf(c11b, Wy1, c10b * Wy0);
        pz = Wx0 * fmaf(a1A, Wz1, a0A * Wz0)
           + Wx1 * fmaf(a1B, Wz1, a0B * Wz0);
    }

    // interleaved-y output: t = x*2+dy is exactly the inner address order
    out[((z * HP + blockIdx.x) * W) * 2 + threadIdx.x] =
        make_float4(vx + px, vy + py, vz + pz, 0.0f);
}

// ---------------------------------------------------------------------------
// Iterations 2..7: quad-lane gather. Block = one x-row: blockIdx.x = y,
// blockIdx.y = z; 640 threads = 160 voxels * 4 lanes.
// Lane sub = t&3: dy = sub&1 (y corner), dx = sub>>1 (x corner).
// Each lane loads its (dy,dx) corner for both z-slices: 2 gather instrs.
// ---------------------------------------------------------------------------
template<bool LAST>
__global__ void __launch_bounds__(640)
integrate_kernel(const float4* __restrict__ in, float4* __restrict__ out4,
                 float* __restrict__ out_soa)
{
    int t   = threadIdx.x;
    int x   = t >> 2;
    int sub = t & 3;
    int dy  = sub & 1;
    int dx  = sub >> 1;
    int y   = blockIdx.x;
    int z   = blockIdx.y;

    float4 v = in[vaddr(x, y, z)];   // same address in all 4 lanes -> broadcast

    float zf = (float)z + v.x;
    float yf = (float)y + v.y;
    float xf = (float)x + v.z;

    int z0 = __float2int_rd(zf);
    int y0 = __float2int_rd(yf);
    int x0 = __float2int_rd(xf);
    float fz = zf - (float)z0;
    float fy = yf - (float)y0;
    float fx = xf - (float)x0;
    int z1 = z0 + 1, y1 = y0 + 1;

    float Wz0 = ((unsigned)z0 < (unsigned)D) ? (1.0f - fz) : 0.0f;
    float Wz1 = ((unsigned)z1 < (unsigned)D) ? fz          : 0.0f;
    float Wy0 = ((unsigned)y0 < (unsigned)H) ? (1.0f - fy) : 0.0f;
    float Wy1 = ((unsigned)y1 < (unsigned)H) ? fy          : 0.0f;
    float Wx0 = ((unsigned)x0 < (unsigned)W) ? (1.0f - fx) : 0.0f;
    float Wx1 = ((unsigned)(x0 + 1) < (unsigned)W) ? fx    : 0.0f;

    int zc0 = min(max(z0, 0), D - 1), zc1 = min(max(z1, 0), D - 1);
    int yc0 = min(max(y0, 0), H - 1), yc1 = min(max(y1, 0), H - 1);
    int xc0 = min(max(x0, 0), W - 1), xc1 = min(max(x0 + 1, 0), W - 1);

    // this lane's corner
    int   py_ = dy ? yc1 : yc0;
    int   px_ = dx ? xc1 : xc0;
    float wyx = (dy ? Wy1 : Wy0) * (dx ? Wx1 : Wx0);

    int rowcol = ((py_ >> 1) * W + px_) * 2 + (py_ & 1);
    int a0 = (zc0 * HP * W) * 2 + rowcol;
    int a1 = (zc1 * HP * W) * 2 + rowcol;

    // 2 gather instructions; for even y0 the 4 lanes of a voxel cover one
    // contiguous 64B window per slice
    float4 c0 = in[a0];
    float4 c1 = in[a1];

    // z-blend, then corner weight; reduce over the 4 lanes
    float qx = fmaf(c1.x, Wz1, c0.x * Wz0) * wyx;
    float qy = fmaf(c1.y, Wz1, c0.y * Wz0) * wyx;
    float qz = fmaf(c1.z, Wz1, c0.z * Wz0) * wyx;

    qx += __shfl_xor_sync(0xFFFFFFFFu, qx, 1);
    qy += __shfl_xor_sync(0xFFFFFFFFu, qy, 1);
    qz += __shfl_xor_sync(0xFFFFFFFFu, qz, 1);
    qx += __shfl_xor_sync(0xFFFFFFFFu, qx, 2);
    qy += __shfl_xor_sync(0xFFFFFFFFu, qy, 2);
    qz += __shfl_xor_sync(0xFFFFFFFFu, qz, 2);

    if (sub == 0) {
        if (!LAST) {
            out4[vaddr(x, y, z)] =
                make_float4(v.x + qx, v.y + qy, v.z + qz, 0.0f);
        } else {
            int idx = (z * H + y) * W + x;   // linear SoA output
            out_soa[idx]            = (v.x + qx) * (1.0f / (0.5f * (D - 1)));
            out_soa[idx + NVOX]     = (v.y + qy) * (1.0f / (0.5f * (H - 1)));
            out_soa[idx + 2 * NVOX] = (v.z + qz) * (1.0f / (0.5f * (W - 1)));
        }
    }
}

extern "C" void kernel_launch(void* const* d_in, const int* in_sizes, int n_in,
                              void* d_out, int out_size)
{
    const float* vec = (const float*)d_in[0];
    float* out = (float*)d_out;

    float4 *bufA, *bufB;
    cudaGetSymbolAddress((void**)&bufA, g_bufA);
    cudaGetSymbolAddress((void**)&bufB, g_bufB);

    dim3 grid1(HP, D);               // (y-pair, z)
    dim3 gridI(H, D);                // (y, z)

    // iteration 1, fused with ingest/scaling, writes interleaved layout
    iter1_kernel<<<grid1, 2 * W>>>(vec, bufA);

    // iterations 2..6
    float4* cur = bufA;
    float4* nxt = bufB;
    for (int i = 0; i < NSTEPS - 2; ++i) {
        integrate_kernel<false><<<gridI, 4 * W>>>(cur, nxt, nullptr);
        float4* tmp = cur; cur = nxt; nxt = tmp;
    }
    // iteration 7, fused with SoA scale-out
    integrate_kernel<true><<<gridI, 4 * W>>>(cur, nullptr, out);
}

// round 9
// speedup vs baseline: 1.2877x; 1.2877x over previous
#include <cuda_runtime.h>

// VecInt: scaling-and-squaring integration of a stationary velocity field.
// vec (1,3,160,192,160) fp32, nsteps=7.
//
// Round 9: R7 configuration restored (best: 502.5us) — pair-lane AoS float4
// integrate for iters 2..7 (measured at the L1tex crossbar floor, ~4.75
// wavefronts/voxel; all structural variants neutral or worse) — plus iter1
// reworked with the same pair-lane split to break its per-thread serial
// chain (27 loads/thread -> 12), keeping the exact R7 arithmetic order
// (bit-identical result).

constexpr int D = 160;
constexpr int H = 192;
constexpr int W = 160;
constexpr int NVOX = D * H * W;          // 4,915,200
constexpr int NSTEPS = 7;

__device__ __align__(128) float4 g_bufA[NVOX];
__device__ __align__(128) float4 g_bufB[NVOX];

// ---------------------------------------------------------------------------
// Iteration 1, fused with SoA ingest + per-channel voxel-unit scaling.
// Pair-lane: 2 lanes per voxel (sub=0 -> x0 column, sub=1 -> x1 column),
// each lane loads 12 scalar corners (4 rows x 3 channels) and blends its
// x-weighted part; shfl-xor(1) reduces the pair. Reduction order matches
// R7's  Wx0*blendA + Wx1*blendB  exactly -> bit-identical.
// Block = one x-row: blockIdx.x = y, blockIdx.y = z, 320 threads.
// ---------------------------------------------------------------------------
__global__ void __launch_bounds__(320)
iter1_kernel(const float* __restrict__ in, float4* __restrict__ out)
{
    int x   = threadIdx.x >> 1;
    int sub = threadIdx.x & 1;
    int y   = blockIdx.x;
    int z   = blockIdx.y;
    int idx = (z * H + y) * W + x;

    const float s  = 1.0f / 128.0f;          // 1/2^7
    const float sD = s * 0.5f * (D - 1);     // channel 0 (z-displacement)
    const float sH = s * 0.5f * (H - 1);     // channel 1 (y)
    const float sW = s * 0.5f * (W - 1);     // channel 2 (x)

    const float* p0 = in;
    const float* p1 = in + NVOX;
    const float* p2 = in + 2 * NVOX;

    float vx = p0[idx] * sD;                 // broadcast across pair lanes
    float vy = p1[idx] * sH;
    float vz = p2[idx] * sW;

    float zf = (float)z + vx;
    float yf = (float)y + vy;
    float xf = (float)x + vz;

    int z0 = __float2int_rd(zf);
    int y0 = __float2int_rd(yf);
    int x0 = __float2int_rd(xf);
    float fz = zf - (float)z0;
    float fy = yf - (float)y0;
    float fx = xf - (float)x0;
    int z1 = z0 + 1, y1 = y0 + 1;

    float Wz0 = ((unsigned)z0 < (unsigned)D) ? (1.0f - fz) : 0.0f;
    float Wz1 = ((unsigned)z1 < (unsigned)D) ? fz          : 0.0f;
    float Wy0 = ((unsigned)y0 < (unsigned)H) ? (1.0f - fy) : 0.0f;
    float Wy1 = ((unsigned)y1 < (unsigned)H) ? fy          : 0.0f;
    float Wx0 = ((unsigned)x0 < (unsigned)W) ? (1.0f - fx) : 0.0f;
    float Wx1 = ((unsigned)(x0 + 1) < (unsigned)W) ? fx    : 0.0f;

    int zc0 = min(max(z0, 0), D - 1), zc1 = min(max(z1, 0), D - 1);
    int yc0 = min(max(y0, 0), H - 1), yc1 = min(max(y1, 0), H - 1);
    int xc0 = min(max(x0, 0), W - 1), xc1 = min(max(x0 + 1, 0), W - 1);

    int   xc = sub ? xc1 : xc0;
    float wx = sub ? Wx1 : Wx0;

    int r00 = (zc0 * H + yc0) * W + xc;
    int r01 = (zc0 * H + yc1) * W + xc;
    int r10 = (zc1 * H + yc0) * W + xc;
    int r11 = (zc1 * H + yc1) * W + xc;

    // channel 0
    float px, py, pz;
    {
        float c00 = p0[r00] * sD;
        float c01 = p0[r01] * sD;
        float c10 = p0[r10] * sD;
        float c11 = p0[r11] * sD;
        float a0 = fmaf(c01, Wy1, c00 * Wy0);
        float a1 = fmaf(c11, Wy1, c10 * Wy0);
        px = wx * fmaf(a1, Wz1, a0 * Wz0);
    }
    // channel 1
    {
        float c00 = p1[r00] * sH;
        float c01 = p1[r01] * sH;
        float c10 = p1[r10] * sH;
        float c11 = p1[r11] * sH;
        float a0 = fmaf(c01, Wy1, c00 * Wy0);
        float a1 = fmaf(c11, Wy1, c10 * Wy0);
        py = wx * fmaf(a1, Wz1, a0 * Wz0);
    }
    // channel 2
    {
        float c00 = p2[r00] * sW;
        float c01 = p2[r01] * sW;
        float c10 = p2[r10] * sW;
        float c11 = p2[r11] * sW;
        float a0 = fmaf(c01, Wy1, c00 * Wy0);
        float a1 = fmaf(c11, Wy1, c10 * Wy0);
        pz = wx * fmaf(a1, Wz1, a0 * Wz0);
    }

    // pair reduce: sub0 holds Wx0-part, sub1 holds Wx1-part.
    // shfl_xor gives sub0: own + other == Wx0*A + Wx1*B (same order as R7).
    px += __shfl_xor_sync(0xFFFFFFFFu, px, 1);
    py += __shfl_xor_sync(0xFFFFFFFFu, py, 1);
    pz += __shfl_xor_sync(0xFFFFFFFFu, pz, 1);

    if (sub == 0)
        out[idx] = make_float4(vx + px, vy + py, vz + pz, 0.0f);
}

// ---------------------------------------------------------------------------
// Iterations 2-7: R5/R7 pair-lane scheme. One x-row per block, 320 threads =
// 160 voxels * 2 lanes; even lane takes x0 corners, odd lane x1.
// ---------------------------------------------------------------------------
template<bool LAST>
__global__ void __launch_bounds__(320)
integrate_kernel(const float4* __restrict__ in, float4* __restrict__ out4,
                 float* __restrict__ out_soa)
{
    int x   = threadIdx.x >> 1;
    int sub = threadIdx.x & 1;
    int y   = blockIdx.x;
    int z   = blockIdx.y;
    int idx = (z * H + y) * W + x;

    float4 v = in[idx];   // same address in both pair lanes -> broadcast

    float zf = (float)z + v.x;
    float yf = (float)y + v.y;
    float xf = (float)x + v.z;

    int z0 = __float2int_rd(zf);
    int y0 = __float2int_rd(yf);
    int x0 = __float2int_rd(xf);
    float fz = zf - (float)z0;
    float fy = yf - (float)y0;
    float fx = xf - (float)x0;
    int z1 = z0 + 1, y1 = y0 + 1;

    float Wz0 = ((unsigned)z0 < (unsigned)D) ? (1.0f - fz) : 0.0f;
    float Wz1 = ((unsigned)z1 < (unsigned)D) ? fz          : 0.0f;
    float Wy0 = ((unsigned)y0 < (unsigned)H) ? (1.0f - fy) : 0.0f;
    float Wy1 = ((unsigned)y1 < (unsigned)H) ? fy          : 0.0f;
    float Wx0 = ((unsigned)x0 < (unsigned)W) ? (1.0f - fx) : 0.0f;
    float Wx1 = ((unsigned)(x0 + 1) < (unsigned)W) ? fx    : 0.0f;

    int zc0 = min(max(z0, 0), D - 1), zc1 = min(max(z1, 0), D - 1);
    int yc0 = min(max(y0, 0), H - 1), yc1 = min(max(y1, 0), H - 1);
    int xc0 = min(max(x0, 0), W - 1), xc1 = min(max(x0 + 1, 0), W - 1);

    int   xc = sub ? xc1 : xc0;
    float wx = sub ? Wx1 : Wx0;

    int r00 = (zc0 * H + yc0) * W + xc;
    int r01 = (zc0 * H + yc1) * W + xc;
    int r10 = (zc1 * H + yc0) * W + xc;
    int r11 = (zc1 * H + yc1) * W + xc;

    float4 c00 = in[r00];
    float4 c01 = in[r01];
    float4 c10 = in[r10];
    float4 c11 = in[r11];

    float px, py, pz;
    {
        float a0 = fmaf(c01.x, Wy1, c00.x * Wy0);
        float a1 = fmaf(c11.x, Wy1, c10.x * Wy0);
        px = wx * fmaf(a1, Wz1, a0 * Wz0);
    }
    {
        float a0 = fmaf(c01.y, Wy1, c00.y * Wy0);
        float a1 = fmaf(c11.y, Wy1, c10.y * Wy0);
        py = wx * fmaf(a1, Wz1, a0 * Wz0);
    }
    {
        float a0 = fmaf(c01.z, Wy1, c00.z * Wy0);
        float a1 = fmaf(c11.z, Wy1, c10.z * Wy0);
        pz = wx * fmaf(a1, Wz1, a0 * Wz0);
    }
    px += __shfl_xor_sync(0xFFFFFFFFu, px, 1);
    py += __shfl_xor_sync(0xFFFFFFFFu, py, 1);
    pz += __shfl_xor_sync(0xFFFFFFFFu, pz, 1);

    if (sub == 0) {
        if (!LAST) {
            float4 r;
            r.x = v.x + px;
            r.y = v.y + py;
            r.z = v.z + pz;
            r.w = 0.0f;
            out4[idx] = r;
        } else {
            out_soa[idx]            = (v.x + px) * (1.0f / (0.5f * (D - 1)));
            out_soa[idx + NVOX]     = (v.y + py) * (1.0f / (0.5f * (H - 1)));
            out_soa[idx + 2 * NVOX] = (v.z + pz) * (1.0f / (0.5f * (W - 1)));
        }
    }
}

extern "C" void kernel_launch(void* const* d_in, const int* in_sizes, int n_in,
                              void* d_out, int out_size)
{
    const float* vec = (const float*)d_in[0];
    float* out = (float*)d_out;

    float4 *bufA, *bufB;
    cudaGetSymbolAddress((void**)&bufA, g_bufA);
    cudaGetSymbolAddress((void**)&bufB, g_bufB);

    dim3 grid(H, D);                 // (y, z)

    // iteration 1, fused with ingest/scaling (pair-lane)
    iter1_kernel<<<grid, 2 * W>>>(vec, bufA);

    // iterations 2..6
    float4* cur = bufA;
    float4* nxt = bufB;
    for (int i = 0; i < NSTEPS - 2; ++i) {
        integrate_kernel<false><<<grid, 2 * W>>>(cur, nxt, nullptr);
        float4* tmp = cur; cur = nxt; nxt = tmp;
    }
    // iteration 7, fused with SoA scale-out
    integrate_kernel<true><<<grid, 2 * W>>>(cur, nullptr, out);
}

// round 10
// speedup vs baseline: 1.3673x; 1.0618x over previous
#include <cuda_runtime.h>

// VecInt: scaling-and-squaring integration of a stationary velocity field.
// vec (1,3,160,192,160) fp32, nsteps=7.
//
// Round 10: exact R7 restoration (proven best, 502.5us) + max-L1 carveout
// hint (kernels use zero smem; reclaim any default smem carveout for L1D).
// R2-R9 established the pair-lane scheme as the measured optimum: scattered
// trilinear gather pinned at ~4.5 L1tex wavefronts/voxel, insensitive to
// occupancy (R3/R5), MLP (R6), line count (R3), and lane count (R8/R9).

constexpr int D = 160;
constexpr int H = 192;
constexpr int W = 160;
constexpr int NVOX = D * H * W;          // 4,915,200
constexpr int NSTEPS = 7;

__device__ __align__(128) float4 g_bufA[NVOX];
__device__ __align__(128) float4 g_bufB[NVOX];

// ---------------------------------------------------------------------------
// Iteration 1, fused with SoA ingest + per-channel voxel-unit scaling.
// One thread per voxel, block = one x-row (160 threads), grid = (H, D).
// ---------------------------------------------------------------------------
__global__ void __launch_bounds__(160)
iter1_kernel(const float* __restrict__ in, float4* __restrict__ out)
{
    int x = threadIdx.x;
    int y = blockIdx.x;
    int z = blockIdx.y;
    int idx = (z * H + y) * W + x;

    const float s  = 1.0f / 128.0f;          // 1/2^7
    const float sD = s * 0.5f * (D - 1);     // channel 0 (z-displacement)
    const float sH = s * 0.5f * (H - 1);     // channel 1 (y)
    const float sW = s * 0.5f * (W - 1);     // channel 2 (x)

    const float* p0 = in;                // channel 0 plane
    const float* p1 = in + NVOX;         // channel 1 plane
    const float* p2 = in + 2 * NVOX;     // channel 2 plane

    float vx = p0[idx] * sD;
    float vy = p1[idx] * sH;
    float vz = p2[idx] * sW;

    float zf = (float)z + vx;
    float yf = (float)y + vy;
    float xf = (float)x + vz;

    int z0 = __float2int_rd(zf);
    int y0 = __float2int_rd(yf);
    int x0 = __float2int_rd(xf);
    float fz = zf - (float)z0;
    float fy = yf - (float)y0;
    float fx = xf - (float)x0;
    int z1 = z0 + 1, y1 = y0 + 1;

    float Wz0 = ((unsigned)z0 < (unsigned)D) ? (1.0f - fz) : 0.0f;
    float Wz1 = ((unsigned)z1 < (unsigned)D) ? fz          : 0.0f;
    float Wy0 = ((unsigned)y0 < (unsigned)H) ? (1.0f - fy) : 0.0f;
    float Wy1 = ((unsigned)y1 < (unsigned)H) ? fy          : 0.0f;
    float Wx0 = ((unsigned)x0 < (unsigned)W) ? (1.0f - fx) : 0.0f;
    float Wx1 = ((unsigned)(x0 + 1) < (unsigned)W) ? fx    : 0.0f;

    int zc0 = min(max(z0, 0), D - 1), zc1 = min(max(z1, 0), D - 1);
    int yc0 = min(max(y0, 0), H - 1), yc1 = min(max(y1, 0), H - 1);
    int xc0 = min(max(x0, 0), W - 1), xc1 = min(max(x0 + 1, 0), W - 1);

    int r00 = (zc0 * H + yc0) * W;
    int r01 = (zc0 * H + yc1) * W;
    int r10 = (zc1 * H + yc0) * W;
    int r11 = (zc1 * H + yc1) * W;

    // per-channel: gather 8 raw corners, scale, blend in the exact R5 order
    // (z/y blend, multiply by this-x weight, then sum x0-part + x1-part).
    float px, py, pz;
    {
        const float* p = p0; const float sc = sD;
        float c00a = p[r00 + xc0] * sc, c00b = p[r00 + xc1] * sc;
        float c01a = p[r01 + xc0] * sc, c01b = p[r01 + xc1] * sc;
        float c10a = p[r10 + xc0] * sc, c10b = p[r10 + xc1] * sc;
        float c11a = p[r11 + xc0] * sc, c11b = p[r11 + xc1] * sc;
        float a0A = fmaf(c01a, Wy1, c00a * Wy0);
        float a1A = fmaf(c11a, Wy1, c10a * Wy0);
        float a0B = fmaf(c01b, Wy1, c00b * Wy0);
        float a1B = fmaf(c11b, Wy1, c10b * Wy0);
        px = Wx0 * fmaf(a1A, Wz1, a0A * Wz0)
           + Wx1 * fmaf(a1B, Wz1, a0B * Wz0);
    }
    {
        const float* p = p1; const float sc = sH;
        float c00a = p[r00 + xc0] * sc, c00b = p[r00 + xc1] * sc;
        float c01a = p[r01 + xc0] * sc, c01b = p[r01 + xc1] * sc;
        float c10a = p[r10 + xc0] * sc, c10b = p[r10 + xc1] * sc;
        float c11a = p[r11 + xc0] * sc, c11b = p[r11 + xc1] * sc;
        float a0A = fmaf(c01a, Wy1, c00a * Wy0);
        float a1A = fmaf(c11a, Wy1, c10a * Wy0);
        float a0B = fmaf(c01b, Wy1, c00b * Wy0);
        float a1B = fmaf(c11b, Wy1, c10b * Wy0);
        py = Wx0 * fmaf(a1A, Wz1, a0A * Wz0)
           + Wx1 * fmaf(a1B, Wz1, a0B * Wz0);
    }
    {
        const float* p = p2; const float sc = sW;
        float c00a = p[r00 + xc0] * sc, c00b = p[r00 + xc1] * sc;
        float c01a = p[r01 + xc0] * sc, c01b = p[r01 + xc1] * sc;
        float c10a = p[r10 + xc0] * sc, c10b = p[r10 + xc1] * sc;
        float c11a = p[r11 + xc0] * sc, c11b = p[r11 + xc1] * sc;
        float a0A = fmaf(c01a, Wy1, c00a * Wy0);
        float a1A = fmaf(c11a, Wy1, c10a * Wy0);
        float a0B = fmaf(c01b, Wy1, c00b * Wy0);
        float a1B = fmaf(c11b, Wy1, c10b * Wy0);
        pz = Wx0 * fmaf(a1A, Wz1, a0A * Wz0)
           + Wx1 * fmaf(a1B, Wz1, a0B * Wz0);
    }

    out[idx] = make_float4(vx + px, vy + py, vz + pz, 0.0f);
}

// ---------------------------------------------------------------------------
// Iterations 2-7: pair-lane scheme. One x-row per block, 320 threads =
// 160 voxels * 2 lanes; even lane takes x0 corners, odd lane x1.
// ---------------------------------------------------------------------------
template<bool LAST>
__global__ void __launch_bounds__(320)
integrate_kernel(const float4* __restrict__ in, float4* __restrict__ out4,
                 float* __restrict__ out_soa)
{
    int x   = threadIdx.x >> 1;
    int sub = threadIdx.x & 1;
    int y   = blockIdx.x;
    int z   = blockIdx.y;
    int idx = (z * H + y) * W + x;

    float4 v = in[idx];   // same address in both pair lanes -> broadcast

    float zf = (float)z + v.x;
    float yf = (float)y + v.y;
    float xf = (float)x + v.z;

    int z0 = __float2int_rd(zf);
    int y0 = __float2int_rd(yf);
    int x0 = __float2int_rd(xf);
    float fz = zf - (float)z0;
    float fy = yf - (float)y0;
    float fx = xf - (float)x0;
    int z1 = z0 + 1, y1 = y0 + 1;

    float Wz0 = ((unsigned)z0 < (unsigned)D) ? (1.0f - fz) : 0.0f;
    float Wz1 = ((unsigned)z1 < (unsigned)D) ? fz          : 0.0f;
    float Wy0 = ((unsigned)y0 < (unsigned)H) ? (1.0f - fy) : 0.0f;
    float Wy1 = ((unsigned)y1 < (unsigned)H) ? fy          : 0.0f;
    float Wx0 = ((unsigned)x0 < (unsigned)W) ? (1.0f - fx) : 0.0f;
    float Wx1 = ((unsigned)(x0 + 1) < (unsigned)W) ? fx    : 0.0f;

    int zc0 = min(max(z0, 0), D - 1), zc1 = min(max(z1, 0), D - 1);
    int yc0 = min(max(y0, 0), H - 1), yc1 = min(max(y1, 0), H - 1);
    int xc0 = min(max(x0, 0), W - 1), xc1 = min(max(x0 + 1, 0), W - 1);

    int   xc = sub ? xc1 : xc0;
    float wx = sub ? Wx1 : Wx0;

    int r00 = (zc0 * H + yc0) * W + xc;
    int r01 = (zc0 * H + yc1) * W + xc;
    int r10 = (zc1 * H + yc0) * W + xc;
    int r11 = (zc1 * H + yc1) * W + xc;

    float4 c00 = in[r00];
    float4 c01 = in[r01];
    float4 c10 = in[r10];
    float4 c11 = in[r11];

    float px, py, pz;
    {
        float a0 = fmaf(c01.x, Wy1, c00.x * Wy0);
        float a1 = fmaf(c11.x, Wy1, c10.x * Wy0);
        px = wx * fmaf(a1, Wz1, a0 * Wz0);
    }
    {
        float a0 = fmaf(c01.y, Wy1, c00.y * Wy0);
        float a1 = fmaf(c11.y, Wy1, c10.y * Wy0);
        py = wx * fmaf(a1, Wz1, a0 * Wz0);
    }
    {
        float a0 = fmaf(c01.z, Wy1, c00.z * Wy0);
        float a1 = fmaf(c11.z, Wy1, c10.z * Wy0);
        pz = wx * fmaf(a1, Wz1, a0 * Wz0);
    }
    px += __shfl_xor_sync(0xFFFFFFFFu, px, 1);
    py += __shfl_xor_sync(0xFFFFFFFFu, py, 1);
    pz += __shfl_xor_sync(0xFFFFFFFFu, pz, 1);

    if (sub == 0) {
        if (!LAST) {
            float4 r;
            r.x = v.x + px;
            r.y = v.y + py;
            r.z = v.z + pz;
            r.w = 0.0f;
            out4[idx] = r;
        } else {
            out_soa[idx]            = (v.x + px) * (1.0f / (0.5f * (D - 1)));
            out_soa[idx + NVOX]     = (v.y + py) * (1.0f / (0.5f * (H - 1)));
            out_soa[idx + 2 * NVOX] = (v.z + pz) * (1.0f / (0.5f * (W - 1)));
        }
    }
}

extern "C" void kernel_launch(void* const* d_in, const int* in_sizes, int n_in,
                              void* d_out, int out_size)
{
    const float* vec = (const float*)d_in[0];
    float* out = (float*)d_out;

    float4 *bufA, *bufB;
    cudaGetSymbolAddress((void**)&bufA, g_bufA);
    cudaGetSymbolAddress((void**)&bufB, g_bufB);

    // kernels use no shared memory: claim the full unified SRAM as L1D.
    static bool carveout_set = false;
    if (!carveout_set) {
        cudaFuncSetAttribute(iter1_kernel,
                             cudaFuncAttributePreferredSharedMemoryCarveout, 0);
        cudaFuncSetAttribute(integrate_kernel<false>,
                             cudaFuncAttributePreferredSharedMemoryCarveout, 0);
        cudaFuncSetAttribute(integrate_kernel<true>,
                             cudaFuncAttributePreferredSharedMemoryCarveout, 0);
        carveout_set = true;
    }

    dim3 grid(H, D);                 // (y, z)

    // iteration 1, fused with ingest/scaling
    iter1_kernel<<<grid, W>>>(vec, bufA);

    // iterations 2..6
    float4* cur = bufA;
    float4* nxt = bufB;
    for (int i = 0; i < NSTEPS - 2; ++i) {
        integrate_kernel<false><<<grid, 2 * W>>>(cur, nxt, nullptr);
        float4* tmp = cur; cur = nxt; nxt = tmp;
    }
    // iteration 7, fused with SoA scale-out
    integrate_kernel<true><<<grid, 2 * W>>>(cur, nullptr, out);
}

// round 11
// speedup vs baseline: 1.3813x; 1.0102x over previous
#include <cuda_runtime.h>

// VecInt: scaling-and-squaring integration of a stationary velocity field.
// vec (1,3,160,192,160) fp32, nsteps=7.
//
// Round 11: R10 kernels (proven optimum: pair-lane gather at the ~4 L1tex
// wavefront/voxel structural floor) + Programmatic Dependent Launch across
// the 7-kernel chain. Each grid signals launch_dependents immediately and
// waits (griddepcontrol.wait) before its first dependent global read, so
// launch latency + prologue + tail-wave drain of consecutive grids overlap.
// Data dependency is preserved exactly: wait blocks until the full upstream
// grid has completed.

constexpr int D = 160;
constexpr int H = 192;
constexpr int W = 160;
constexpr int NVOX = D * H * W;          // 4,915,200
constexpr int NSTEPS = 7;

__device__ __align__(128) float4 g_bufA[NVOX];
__device__ __align__(128) float4 g_bufB[NVOX];

__device__ __forceinline__ void pdl_launch_dependents() {
    asm volatile("griddepcontrol.launch_dependents;" ::: "memory");
}
__device__ __forceinline__ void pdl_wait() {
    asm volatile("griddepcontrol.wait;" ::: "memory");
}

// ---------------------------------------------------------------------------
// Iteration 1, fused with SoA ingest + per-channel voxel-unit scaling.
// One thread per voxel, block = one x-row (160 threads), grid = (H, D).
// ---------------------------------------------------------------------------
__global__ void __launch_bounds__(160)
iter1_kernel(const float* __restrict__ in, float4* __restrict__ out)
{
    int x = threadIdx.x;
    int y = blockIdx.x;
    int z = blockIdx.y;
    int idx = (z * H + y) * W + x;

    // input is external (not produced by a PDL-chained grid) — no wait needed,
    // but signal dependents so iteration 2 can spin up under our execution.
    pdl_launch_dependents();

    const float s  = 1.0f / 128.0f;          // 1/2^7
    const float sD = s * 0.5f * (D - 1);     // channel 0 (z-displacement)
    const float sH = s * 0.5f * (H - 1);     // channel 1 (y)
    const float sW = s * 0.5f * (W - 1);     // channel 2 (x)

    const float* p0 = in;                // channel 0 plane
    const float* p1 = in + NVOX;         // channel 1 plane
    const float* p2 = in + 2 * NVOX;     // channel 2 plane

    float vx = p0[idx] * sD;
    float vy = p1[idx] * sH;
    float vz = p2[idx] * sW;

    float zf = (float)z + vx;
    float yf = (float)y + vy;
    float xf = (float)x + vz;

    int z0 = __float2int_rd(zf);
    int y0 = __float2int_rd(yf);
    int x0 = __float2int_rd(xf);
    float fz = zf - (float)z0;
    float fy = yf - (float)y0;
    float fx = xf - (float)x0;
    int z1 = z0 + 1, y1 = y0 + 1;

    float Wz0 = ((unsigned)z0 < (unsigned)D) ? (1.0f - fz) : 0.0f;
    float Wz1 = ((unsigned)z1 < (unsigned)D) ? fz          : 0.0f;
    float Wy0 = ((unsigned)y0 < (unsigned)H) ? (1.0f - fy) : 0.0f;
    float Wy1 = ((unsigned)y1 < (unsigned)H) ? fy          : 0.0f;
    float Wx0 = ((unsigned)x0 < (unsigned)W) ? (1.0f - fx) : 0.0f;
    float Wx1 = ((unsigned)(x0 + 1) < (unsigned)W) ? fx    : 0.0f;

    int zc0 = min(max(z0, 0), D - 1), zc1 = min(max(z1, 0), D - 1);
    int yc0 = min(max(y0, 0), H - 1), yc1 = min(max(y1, 0), H - 1);
    int xc0 = min(max(x0, 0), W - 1), xc1 = min(max(x0 + 1, 0), W - 1);

    int r00 = (zc0 * H + yc0) * W;
    int r01 = (zc0 * H + yc1) * W;
    int r10 = (zc1 * H + yc0) * W;
    int r11 = (zc1 * H + yc1) * W;

    float px, py, pz;
    {
        const float* p = p0; const float sc = sD;
        float c00a = p[r00 + xc0] * sc, c00b = p[r00 + xc1] * sc;
        float c01a = p[r01 + xc0] * sc, c01b = p[r01 + xc1] * sc;
        float c10a = p[r10 + xc0] * sc, c10b = p[r10 + xc1] * sc;
        float c11a = p[r11 + xc0] * sc, c11b = p[r11 + xc1] * sc;
        float a0A = fmaf(c01a, Wy1, c00a * Wy0);
        float a1A = fmaf(c11a, Wy1, c10a * Wy0);
        float a0B = fmaf(c01b, Wy1, c00b * Wy0);
        float a1B = fmaf(c11b, Wy1, c10b * Wy0);
        px = Wx0 * fmaf(a1A, Wz1, a0A * Wz0)
           + Wx1 * fmaf(a1B, Wz1, a0B * Wz0);
    }
    {
        const float* p = p1; const float sc = sH;
        float c00a = p[r00 + xc0] * sc, c00b = p[r00 + xc1] * sc;
        float c01a = p[r01 + xc0] * sc, c01b = p[r01 + xc1] * sc;
        float c10a = p[r10 + xc0] * sc, c10b = p[r10 + xc1] * sc;
        float c11a = p[r11 + xc0] * sc, c11b = p[r11 + xc1] * sc;
        float a0A = fmaf(c01a, Wy1, c00a * Wy0);
        float a1A = fmaf(c11a, Wy1, c10a * Wy0);
        float a0B = fmaf(c01b, Wy1, c00b * Wy0);
        float a1B = fmaf(c11b, Wy1, c10b * Wy0);
        py = Wx0 * fmaf(a1A, Wz1, a0A * Wz0)
           + Wx1 * fmaf(a1B, Wz1, a0B * Wz0);
    }
    {
        const float* p = p2; const float sc = sW;
        float c00a = p[r00 + xc0] * sc, c00b = p[r00 + xc1] * sc;
        float c01a = p[r01 + xc0] * sc, c01b = p[r01 + xc1] * sc;
        float c10a = p[r10 + xc0] * sc, c10b = p[r10 + xc1] * sc;
        float c11a = p[r11 + xc0] * sc, c11b = p[r11 + xc1] * sc;
        float a0A = fmaf(c01a, Wy1, c00a * Wy0);
        float a1A = fmaf(c11a, Wy1, c10a * Wy0);
        float a0B = fmaf(c01b, Wy1, c00b * Wy0);
        float a1B = fmaf(c11b, Wy1, c10b * Wy0);
        pz = Wx0 * fmaf(a1A, Wz1, a0A * Wz0)
           + Wx1 * fmaf(a1B, Wz1, a0B * Wz0);
    }

    out[idx] = make_float4(vx + px, vy + py, vz + pz, 0.0f);
}

// ---------------------------------------------------------------------------
// Iterations 2-7: pair-lane scheme. One x-row per block, 320 threads =
// 160 voxels * 2 lanes; even lane takes x0 corners, odd lane x1.
// ---------------------------------------------------------------------------
template<bool LAST>
__global__ void __launch_bounds__(320)
integrate_kernel(const float4* __restrict__ in, float4* __restrict__ out4,
                 float* __restrict__ out_soa)
{
    int x   = threadIdx.x >> 1;
    int sub = threadIdx.x & 1;
    int y   = blockIdx.x;
    int z   = blockIdx.y;
    int idx = (z * H + y) * W + x;

    // let the next grid spin up; wait for the producer grid before reading.
    pdl_launch_dependents();
    pdl_wait();

    float4 v = in[idx];   // same address in both pair lanes -> broadcast

    float zf = (float)z + v.x;
    float yf = (float)y + v.y;
    float xf = (float)x + v.z;

    int z0 = __float2int_rd(zf);
    int y0 = __float2int_rd(yf);
    int x0 = __float2int_rd(xf);
    float fz = zf - (float)z0;
    float fy = yf - (float)y0;
    float fx = xf - (float)x0;
    int z1 = z0 + 1, y1 = y0 + 1;

    float Wz0 = ((unsigned)z0 < (unsigned)D) ? (1.0f - fz) : 0.0f;
    float Wz1 = ((unsigned)z1 < (unsigned)D) ? fz          : 0.0f;
    float Wy0 = ((unsigned)y0 < (unsigned)H) ? (1.0f - fy) : 0.0f;
    float Wy1 = ((unsigned)y1 < (unsigned)H) ? fy          : 0.0f;
    float Wx0 = ((unsigned)x0 < (unsigned)W) ? (1.0f - fx) : 0.0f;
    float Wx1 = ((unsigned)(x0 + 1) < (unsigned)W) ? fx    : 0.0f;

    int zc0 = min(max(z0, 0), D - 1), zc1 = min(max(z1, 0), D - 1);
    int yc0 = min(max(y0, 0), H - 1), yc1 = min(max(y1, 0), H - 1);
    int xc0 = min(max(x0, 0), W - 1), xc1 = min(max(x0 + 1, 0), W - 1);

    int   xc = sub ? xc1 : xc0;
    float wx = sub ? Wx1 : Wx0;

    int r00 = (zc0 * H + yc0) * W + xc;
    int r01 = (zc0 * H + yc1) * W + xc;
    int r10 = (zc1 * H + yc0) * W + xc;
    int r11 = (zc1 * H + yc1) * W + xc;

    float4 c00 = in[r00];
    float4 c01 = in[r01];
    float4 c10 = in[r10];
    float4 c11 = in[r11];

    float px, py, pz;
    {
        float a0 = fmaf(c01.x, Wy1, c00.x * Wy0);
        float a1 = fmaf(c11.x, Wy1, c10.x * Wy0);
        px = wx * fmaf(a1, Wz1, a0 * Wz0);
    }
    {
        float a0 = fmaf(c01.y, Wy1, c00.y * Wy0);
        float a1 = fmaf(c11.y, Wy1, c10.y * Wy0);
        py = wx * fmaf(a1, Wz1, a0 * Wz0);
    }
    {
        float a0 = fmaf(c01.z, Wy1, c00.z * Wy0);
        float a1 = fmaf(c11.z, Wy1, c10.z * Wy0);
        pz = wx * fmaf(a1, Wz1, a0 * Wz0);
    }
    px += __shfl_xor_sync(0xFFFFFFFFu, px, 1);
    py += __shfl_xor_sync(0xFFFFFFFFu, py, 1);
    pz += __shfl_xor_sync(0xFFFFFFFFu, pz, 1);

    if (sub == 0) {
        if (!LAST) {
            float4 r;
            r.x = v.x + px;
            r.y = v.y + py;
            r.z = v.z + pz;
            r.w = 0.0f;
            out4[idx] = r;
        } else {
            out_soa[idx]            = (v.x + px) * (1.0f / (0.5f * (D - 1)));
            out_soa[idx + NVOX]     = (v.y + py) * (1.0f / (0.5f * (H - 1)));
            out_soa[idx + 2 * NVOX] = (v.z + pz) * (1.0f / (0.5f * (W - 1)));
        }
    }
}

static void launch_pdl(void* func, dim3 grid, dim3 block,
                       void** args)
{
    cudaLaunchConfig_t cfg = {};
    cfg.gridDim  = grid;
    cfg.blockDim = block;
    cfg.dynamicSmemBytes = 0;
    cfg.stream = 0;
    cudaLaunchAttribute attr[1];
    attr[0].id = cudaLaunchAttributeProgrammaticStreamSerialization;
    attr[0].val.programmaticStreamSerializationAllowed = 1;
    cfg.attrs = attr;
    cfg.numAttrs = 1;
    cudaLaunchKernelExC(&cfg, func, args);
}

extern "C" void kernel_launch(void* const* d_in, const int* in_sizes, int n_in,
                              void* d_out, int out_size)
{
    const float* vec = (const float*)d_in[0];
    float* out = (float*)d_out;

    float4 *bufA, *bufB;
    cudaGetSymbolAddress((void**)&bufA, g_bufA);
    cudaGetSymbolAddress((void**)&bufB, g_bufB);

    dim3 grid(H, D);                 // (y, z)

    // iteration 1, fused with ingest/scaling
    {
        const float* a0 = vec; float4* a1 = bufA;
        void* args[] = { &a0, &a1 };
        launch_pdl((void*)iter1_kernel, grid, dim3(W), args);
    }

    // iterations 2..6
    float4* cur = bufA;
    float4* nxt = bufB;
    for (int i = 0; i < NSTEPS - 2; ++i) {
        const float4* a0 = cur; float4* a1 = nxt; float* a2 = nullptr;
        void* args[] = { &a0, &a1, &a2 };
        launch_pdl((void*)integrate_kernel<false>, grid, dim3(2 * W), args);
        float4* tmp = cur; cur = nxt; nxt = tmp;
    }
    // iteration 7, fused with SoA scale-out
    {
        const float4* a0 = cur; float4* a1 = nullptr; float* a2 = out;
        void* args[] = { &a0, &a1, &a2 };
        launch_pdl((void*)integrate_kernel<true>, grid, dim3(2 * W), args);
    }
}